// round 10
// baseline (speedup 1.0000x reference)
#include <cuda_runtime.h>
#include <cstdint>
#include <cstddef>

// ---------------------------------------------------------------------------
// Problem dims
// ---------------------------------------------------------------------------
#define B_DIM   8192
#define IN_DIM  4096
#define OUT_DIM 2048

// GEMM tiling: CTA computes 128x128; cols 0-95 via IMMA, cols 96-127 via popcount
#define BM 128
#define BN 128
#define N_IMMA 96
#define N_POP  32
#define BK 64
#define KSTEPS (IN_DIM / BK)        // 64
#define NBUF 4                      // 4 smem buffers, prefetch depth 3

// Smem stage: int8 tiles (rows padded to 80B, conflict-free 4B loads) + bit tiles
#define ROW_STRIDE 80
#define A_BYTES (BM * ROW_STRIDE)   // 10240
#define B_BYTES (BN * ROW_STRIDE)   // 10240
#define XB_OFF  (A_BYTES + B_BYTES) // 20480: 128 rows x 8B x-bits
#define WB_OFF  (XB_OFF + BM * 8)   // 21504: 32 cols x 8B w-bits
#define STAGE_BYTES (WB_OFF + N_POP * 8)          // 21760
#define SMEM_SCALE 0                               // 128 floats
#define SMEM_AB    1024
#define SMEM_TOTAL (SMEM_AB + NBUF * STAGE_BYTES)  // 88064

// ---------------------------------------------------------------------------
// Scratch (device globals: allocation-free rule). Referenced ONLY from device
// code — passing these as kernel args from host was the rounds-6..8 bug
// (host-side symbol address is not the device address).
// ---------------------------------------------------------------------------
__device__ __align__(16) int8_t   g_Xb[(size_t)B_DIM * IN_DIM];           // sign(X) int8, K-major
__device__ __align__(16) int8_t   g_Wb[(size_t)OUT_DIM * IN_DIM];         // sign(W)^T int8, K-major
__device__ __align__(16) uint32_t g_Xbits[(size_t)B_DIM * (IN_DIM/32)];   // 1 = negative
__device__ __align__(16) uint32_t g_Wbits[(size_t)OUT_DIM * (IN_DIM/32)];

// ---------------------------------------------------------------------------
// Helpers (sm_80-compatible PTX only)
// ---------------------------------------------------------------------------
__device__ __forceinline__ uint32_t smem_u32(const void* p) {
    uint32_t a;
    asm("{ .reg .u64 t; cvta.to.shared.u64 t, %1; cvt.u32.u64 %0, t; }" : "=r"(a) : "l"(p));
    return a;
}
__device__ __forceinline__ void cp_async16(uint32_t dst, const void* src) {
    asm volatile("cp.async.cg.shared.global [%0], [%1], 16;" :: "r"(dst), "l"(src) : "memory");
}
__device__ __forceinline__ void cp_async8(uint32_t dst, const void* src) {
    asm volatile("cp.async.ca.shared.global [%0], [%1], 8;" :: "r"(dst), "l"(src) : "memory");
}
__device__ __forceinline__ void mma_s8(int* c, const uint32_t* a, const uint32_t* b) {
    asm volatile(
        "mma.sync.aligned.m16n8k32.row.col.s32.s8.s8.s32 "
        "{%0,%1,%2,%3}, {%4,%5,%6,%7}, {%8,%9}, {%0,%1,%2,%3};"
        : "+r"(c[0]), "+r"(c[1]), "+r"(c[2]), "+r"(c[3])
        : "r"(a[0]), "r"(a[1]), "r"(a[2]), "r"(a[3]), "r"(b[0]), "r"(b[1]));
}
__device__ __forceinline__ uint32_t sign_byte(uint32_t fbits) {
    // 0x01 for >=0, 0xFF (-1) for negative
    return 0x01u ^ (0xFEu & (uint32_t)(-(int32_t)(fbits >> 31)));
}
// Sign-bit nibble of 4 packed sign-bytes (bit set = negative)
__device__ __forceinline__ uint32_t nib4(uint32_t v) {
    return ((v >> 7) & 1u) | ((v >> 14) & 2u) | ((v >> 21) & 4u) | ((v >> 28) & 8u);
}
__device__ __forceinline__ uint32_t pack32(const uint32_t* src, size_t i) {
    uint4 v0 = reinterpret_cast<const uint4*>(src)[i * 2];
    uint4 v1 = reinterpret_cast<const uint4*>(src)[i * 2 + 1];
    return nib4(v0.x)
         | (nib4(v0.y) << 4)
         | (nib4(v0.z) << 8)
         | (nib4(v0.w) << 12)
         | (nib4(v1.x) << 16)
         | (nib4(v1.y) << 20)
         | (nib4(v1.z) << 24)
         | (nib4(v1.w) << 28);
}

// ---------------------------------------------------------------------------
// Kernel 1: quantize X -> int8 {+1,-1}, [B, IN] K-major
// ---------------------------------------------------------------------------
__global__ void __launch_bounds__(256) quant_x_kernel(const float* __restrict__ X) {
    size_t i = (size_t)blockIdx.x * blockDim.x + threadIdx.x;   // uint4 index
    uint4 v = reinterpret_cast<const uint4*>(X)[i];
    uint32_t p = sign_byte(v.x) | (sign_byte(v.y) << 8)
               | (sign_byte(v.z) << 16) | (sign_byte(v.w) << 24);
    reinterpret_cast<uint32_t*>(g_Xb)[i] = p;
}

// ---------------------------------------------------------------------------
// Kernel 2: quantize + transpose W[IN,OUT] -> Wb[OUT,IN] int8 {+1,-1}
// ---------------------------------------------------------------------------
__global__ void __launch_bounds__(256) quant_w_kernel(const float* __restrict__ W) {
    __shared__ uint8_t tile[32][33];
    int n0 = blockIdx.x * 32, k0 = blockIdx.y * 32;
    int tx = threadIdx.x, ty = threadIdx.y;
#pragma unroll
    for (int j = 0; j < 4; j++) {
        int kk = ty + j * 8;
        tile[kk][tx] = (uint8_t)sign_byte(__float_as_uint(W[(size_t)(k0 + kk) * OUT_DIM + n0 + tx]));
    }
    __syncthreads();
    int t = tx + ty * 32;
    int nn = t >> 3;            // 0..31
    int kk = (t & 7) * 4;       // 0..28
    uint32_t p = (uint32_t)tile[kk + 0][nn]
               | ((uint32_t)tile[kk + 1][nn] << 8)
               | ((uint32_t)tile[kk + 2][nn] << 16)
               | ((uint32_t)tile[kk + 3][nn] << 24);
    *reinterpret_cast<uint32_t*>(&g_Wb[(size_t)(n0 + nn) * IN_DIM + k0 + kk]) = p;
}

// ---------------------------------------------------------------------------
// Kernels 2b/2c: bit-pack int8 signs -> 1 bit per value (1 = negative),
// k-order. One thread packs 32 consecutive int8 into one u32. Globals
// referenced directly (no pointer args).
// ---------------------------------------------------------------------------
__global__ void __launch_bounds__(256) bitpack_x_kernel() {
    size_t i = (size_t)blockIdx.x * blockDim.x + threadIdx.x;
    g_Xbits[i] = pack32(reinterpret_cast<const uint32_t*>(g_Xb), i);
}
__global__ void __launch_bounds__(256) bitpack_w_kernel() {
    size_t i = (size_t)blockIdx.x * blockDim.x + threadIdx.x;
    g_Wbits[i] = pack32(reinterpret_cast<const uint32_t*>(g_Wb), i);
}

// ---------------------------------------------------------------------------
// Kernel 3: hybrid GEMM. Tensor pipe (IMMA, cols 0-95) + ALU pipe (XOR-popc,
// cols 96-127) run concurrently in the same mainloop.
// Register budget: acc 48 + pacc 8 (two rows packed per reg) + frag peak 10.
//   D[m,n] = sum_k Xb[m,k]*Wb[n,k] (exact int); out = float(D) * scale[n]
// ---------------------------------------------------------------------------
__global__ void __launch_bounds__(256, 2) gemm_kernel(
    const float* __restrict__ alpha, const float* __restrict__ betta,
    const float* __restrict__ gamma, float* __restrict__ out)
{
    extern __shared__ char smem[];
    uint32_t sb = smem_u32(smem);
    int tid = threadIdx.x, wid = tid >> 5, lane = tid & 31;
    int warp_m = wid >> 2, warp_n = wid & 3;        // 2 x 4 warp grid (IMMA part)
    int g = lane >> 2, q = lane & 3;
    int n0 = blockIdx.x * BN, m0 = blockIdx.y * BM;

    if (tid < BN) {   // per-column scale
        int n = n0 + tid;
        float s = fmaxf(__ldg(alpha), 0.f) * fmaxf(__ldg(&betta[n >> 6]), 0.f)
                * fmaxf(__ldg(&gamma[n & 63]), 0.f);
        reinterpret_cast<float*>(smem + SMEM_SCALE)[tid] = s;
    }

    // Stage fill: 1024 x 16B int8 chunks + 160 x 8B bit chunks
    auto fill = [&](int ks) {
        uint32_t dst = sb + SMEM_AB + (ks & (NBUF - 1)) * STAGE_BYTES;
        size_t ksrc = (size_t)ks * BK;
#pragma unroll
        for (int i = 0; i < 4; i++) {
            int c = tid + i * 256;
            if (c < 512) {
                int row = c >> 2, q16 = c & 3;
                cp_async16(dst + row * ROW_STRIDE + q16 * 16,
                           g_Xb + (size_t)(m0 + row) * IN_DIM + ksrc + q16 * 16);
            } else {
                int c2 = c - 512;
                int row = c2 >> 2, q16 = c2 & 3;
                cp_async16(dst + A_BYTES + row * ROW_STRIDE + q16 * 16,
                           g_Wb + (size_t)(n0 + row) * IN_DIM + ksrc + q16 * 16);
            }
        }
        if (tid < 128) {
            cp_async8(dst + XB_OFF + tid * 8,
                      g_Xbits + (size_t)(m0 + tid) * (IN_DIM / 32) + ks * 2);
        } else if (tid < 128 + N_POP) {
            int c = tid - 128;
            cp_async8(dst + WB_OFF + c * 8,
                      g_Wbits + (size_t)(n0 + N_IMMA + c) * (IN_DIM / 32) + ks * 2);
        }
        asm volatile("cp.async.commit_group;" ::: "memory");
    };

    int acc[4][3][4];        // IMMA: 64 rows x 24 cols per warp
#pragma unroll
    for (int mi = 0; mi < 4; mi++)
#pragma unroll
        for (int nj = 0; nj < 3; nj++)
#pragma unroll
            for (int r = 0; r < 4; r++) acc[mi][nj][r] = 0;

    // Popcount: warp wid owns rows wid*16..+15, lane owns col 96+lane.
    // Two rows packed per reg: low 16 = row 2r, high 16 = row 2r+1 (max 4096 each).
    uint32_t pacc[8];
#pragma unroll
    for (int r = 0; r < 8; r++) pacc[r] = 0;

    fill(0); fill(1); fill(2);

    for (int ks = 0; ks < KSTEPS; ks++) {
        asm volatile("cp.async.wait_group 2;" ::: "memory");   // stage ks resident
        __syncthreads();

        const char* stage = smem + SMEM_AB + (ks & (NBUF - 1)) * STAGE_BYTES;
        const char* sA = stage;
        const char* sB = stage + A_BYTES;

        // --- tensor pipe: IMMA over cols 0-95 (b first, then a per-mi: low reg peak)
#pragma unroll
        for (int kk = 0; kk < 2; kk++) {
            int ko = kk * 32;
            uint32_t b[3][2];
#pragma unroll
            for (int nj = 0; nj < 3; nj++) {
                const char* pb = sB + (warp_n * 24 + nj * 8 + g) * ROW_STRIDE + q * 4 + ko;
                b[nj][0] = *reinterpret_cast<const uint32_t*>(pb);
                b[nj][1] = *reinterpret_cast<const uint32_t*>(pb + 16);
            }
#pragma unroll
            for (int mi = 0; mi < 4; mi++) {
                uint32_t a[4];
                const char* pa = sA + (warp_m * 64 + mi * 16 + g) * ROW_STRIDE + q * 4 + ko;
                a[0] = *reinterpret_cast<const uint32_t*>(pa);
                a[1] = *reinterpret_cast<const uint32_t*>(pa + 8 * ROW_STRIDE);
                a[2] = *reinterpret_cast<const uint32_t*>(pa + 16);
                a[3] = *reinterpret_cast<const uint32_t*>(pa + 8 * ROW_STRIDE + 16);
#pragma unroll
                for (int nj = 0; nj < 3; nj++)
                    mma_s8(acc[mi][nj], a, b[nj]);
            }
        }

        // --- alu pipe: XOR-popcount over cols 96-127 (64 k-bits = uint2) ---
        {
            uint2 wv = *reinterpret_cast<const uint2*>(stage + WB_OFF + lane * 8);
            const uint2* xp = reinterpret_cast<const uint2*>(stage + XB_OFF + wid * 16 * 8);
#pragma unroll
            for (int r = 0; r < 8; r++) {
                uint2 x0 = xp[2 * r];          // warp-uniform broadcast LDS
                uint2 x1 = xp[2 * r + 1];
                uint32_t c0 = __popc(x0.x ^ wv.x) + __popc(x0.y ^ wv.y);
                uint32_t c1 = __popc(x1.x ^ wv.x) + __popc(x1.y ^ wv.y);
                pacc[r] += c0 + (c1 << 16);
            }
        }

        // Buffer (ks+3)&3 held stage ks-1, consumed before the __syncthreads above.
        if (ks + 3 < KSTEPS) fill(ks + 3);
        else asm volatile("cp.async.commit_group;" ::: "memory");  // uniform accounting
    }

    __syncthreads();
    const float* sc = reinterpret_cast<const float*>(smem + SMEM_SCALE);

    // IMMA epilogue (cols 0-95)
#pragma unroll
    for (int mi = 0; mi < 4; mi++) {
        int r0 = m0 + warp_m * 64 + mi * 16 + g;
#pragma unroll
        for (int nj = 0; nj < 3; nj++) {
            int col = warp_n * 24 + nj * 8 + 2 * q;
            float s0 = sc[col], s1 = sc[col + 1];
            float2 v0 = make_float2((float)acc[mi][nj][0] * s0, (float)acc[mi][nj][1] * s1);
            float2 v1 = make_float2((float)acc[mi][nj][2] * s0, (float)acc[mi][nj][3] * s1);
            *reinterpret_cast<float2*>(out + (size_t)r0 * OUT_DIM + n0 + col) = v0;
            *reinterpret_cast<float2*>(out + (size_t)(r0 + 8) * OUT_DIM + n0 + col) = v1;
        }
    }
    // Popcount epilogue (cols 96-127): dot = K - 2*mismatches
    {
        float s = sc[N_IMMA + lane];
        int colg = n0 + N_IMMA + lane;
#pragma unroll
        for (int r = 0; r < 8; r++) {
            int row = m0 + wid * 16 + 2 * r;
            uint32_t c0 = pacc[r] & 0xFFFFu, c1 = pacc[r] >> 16;
            out[(size_t)row * OUT_DIM + colg]       = (float)(int)(IN_DIM - 2 * c0) * s;
            out[(size_t)(row + 1) * OUT_DIM + colg] = (float)(int)(IN_DIM - 2 * c1) * s;
        }
    }
}

// ---------------------------------------------------------------------------
// Launch
// ---------------------------------------------------------------------------
extern "C" void kernel_launch(void* const* d_in, const int* in_sizes, int n_in,
                              void* d_out, int out_size) {
    const float *X = nullptr, *W = nullptr, *alpha = nullptr, *betta = nullptr, *gamma = nullptr;
    for (int i = 0; i < n_in; i++) {
        switch (in_sizes[i]) {
            case B_DIM * IN_DIM:   X     = (const float*)d_in[i]; break;  // 33554432
            case IN_DIM * OUT_DIM: W     = (const float*)d_in[i]; break;  // 8388608
            case 1:                alpha = (const float*)d_in[i]; break;
            case 32:               betta = (const float*)d_in[i]; break;
            case 64:               gamma = (const float*)d_in[i]; break;
        }
    }
    cudaFuncSetAttribute(gemm_kernel, cudaFuncAttributeMaxDynamicSharedMemorySize, SMEM_TOTAL);

    quant_x_kernel<<<(B_DIM * (size_t)IN_DIM) / 4 / 256, 256>>>(X);
    quant_w_kernel<<<dim3(OUT_DIM / 32, IN_DIM / 32), dim3(32, 8)>>>(W);
    bitpack_x_kernel<<<(B_DIM * (size_t)(IN_DIM / 32)) / 256, 256>>>();
    bitpack_w_kernel<<<(OUT_DIM * (size_t)(IN_DIM / 32)) / 256, 256>>>();
    gemm_kernel<<<dim3(OUT_DIM / BN, B_DIM / BM), 256, SMEM_TOTAL>>>(
        alpha, betta, gamma, (float*)d_out);
}

// round 11
// speedup vs baseline: 1.3768x; 1.3768x over previous
#include <cuda_runtime.h>
#include <cstdint>
#include <cstddef>

// ---------------------------------------------------------------------------
// Problem dims
// ---------------------------------------------------------------------------
#define B_DIM   8192
#define IN_DIM  4096
#define OUT_DIM 2048

// GEMM tiling (round-5 configuration: pure IMMA, measured at the 1024
// int8-MAC/cyc/SM legacy-mma ceiling)
#define BM 128
#define BN 128
#define BK 64
#define KSTEPS (IN_DIM / BK)        // 64
#define NBUF 4                      // 4 smem buffers, prefetch depth 3

// Smem: rows padded to 80B so 4B fragment loads are bank-conflict-free
#define ROW_STRIDE 80
#define A_BYTES (BM * ROW_STRIDE)   // 10240
#define B_BYTES (BN * ROW_STRIDE)   // 10240
#define STAGE_BYTES (A_BYTES + B_BYTES)          // 20480
#define SMEM_SCALE 0                              // 128 floats
#define SMEM_AB    1024
#define SMEM_TOTAL (SMEM_AB + NBUF * STAGE_BYTES) // 82944

// ---------------------------------------------------------------------------
// Scratch (device globals; referenced only from device code)
// ---------------------------------------------------------------------------
__device__ __align__(16) int8_t g_Xb[(size_t)B_DIM * IN_DIM];    // sign(X), K-major
__device__ __align__(16) int8_t g_Wb[(size_t)OUT_DIM * IN_DIM];  // sign(W)^T, K-major

// ---------------------------------------------------------------------------
// Helpers (sm_80-compatible PTX only)
// ---------------------------------------------------------------------------
__device__ __forceinline__ uint32_t smem_u32(const void* p) {
    uint32_t a;
    asm("{ .reg .u64 t; cvta.to.shared.u64 t, %1; cvt.u32.u64 %0, t; }" : "=r"(a) : "l"(p));
    return a;
}
__device__ __forceinline__ void cp_async16(uint32_t dst, const void* src) {
    asm volatile("cp.async.cg.shared.global [%0], [%1], 16;" :: "r"(dst), "l"(src) : "memory");
}
__device__ __forceinline__ void mma_s8(int* c, const uint32_t* a, const uint32_t* b) {
    asm volatile(
        "mma.sync.aligned.m16n8k32.row.col.s32.s8.s8.s32 "
        "{%0,%1,%2,%3}, {%4,%5,%6,%7}, {%8,%9}, {%0,%1,%2,%3};"
        : "+r"(c[0]), "+r"(c[1]), "+r"(c[2]), "+r"(c[3])
        : "r"(a[0]), "r"(a[1]), "r"(a[2]), "r"(a[3]), "r"(b[0]), "r"(b[1]));
}
__device__ __forceinline__ uint32_t sign_byte(uint32_t fbits) {
    // 0x01 for >=0, 0xFF (-1) for negative
    return 0x01u ^ (0xFEu & (uint32_t)(-(int32_t)(fbits >> 31)));
}
__device__ __forceinline__ uint4 ldcs4(const uint4* p) {
    uint4 v;
    asm volatile("ld.global.cs.v4.u32 {%0,%1,%2,%3}, [%4];"
                 : "=r"(v.x), "=r"(v.y), "=r"(v.z), "=r"(v.w) : "l"(p));
    return v;
}
__device__ __forceinline__ void stcs2(uint2* p, uint2 v) {
    asm volatile("st.global.cs.v2.u32 [%0], {%1,%2};" :: "l"(p), "r"(v.x), "r"(v.y) : "memory");
}

// ---------------------------------------------------------------------------
// Kernel 1: quantize X -> int8 {+1,-1}, [B, IN] K-major.
// Streaming (evict-first) loads/stores: X is read once, signs written once;
// keep both out of L2 so the GEMM's W tiles aren't evicted.
// Grid-stride: 2 uint4 per thread.
// ---------------------------------------------------------------------------
__global__ void __launch_bounds__(256) quant_x_kernel(const float* __restrict__ X) {
    size_t i0 = (size_t)blockIdx.x * (blockDim.x * 2) + threadIdx.x;
#pragma unroll
    for (int j = 0; j < 2; j++) {
        size_t i = i0 + j * 256;
        uint4 v = ldcs4(reinterpret_cast<const uint4*>(X) + i);
        uint32_t lo = sign_byte(v.x) | (sign_byte(v.y) << 8);
        uint32_t hi = sign_byte(v.z) | (sign_byte(v.w) << 8);
        uint2 p = make_uint2(lo | (hi << 16), 0);
        // repack: bytes must be x,y,z,w consecutively
        p.x = sign_byte(v.x) | (sign_byte(v.y) << 8) | (sign_byte(v.z) << 16) | (sign_byte(v.w) << 24);
        uint4 v2 = ldcs4(reinterpret_cast<const uint4*>(X) + i + (size_t)gridDim.x * 512);
        p.y = sign_byte(v2.x) | (sign_byte(v2.y) << 8) | (sign_byte(v2.z) << 16) | (sign_byte(v2.w) << 24);
        // store 2 packed words: positions i and i + gridDim.x*512 -> must store separately
        reinterpret_cast<uint32_t*>(g_Xb)[i] = p.x;
        reinterpret_cast<uint32_t*>(g_Xb)[i + (size_t)gridDim.x * 512] = p.y;
    }
}

// ---------------------------------------------------------------------------
// Kernel 2: quantize + transpose W[IN,OUT] -> Wb[OUT,IN] int8 {+1,-1}
// ---------------------------------------------------------------------------
__global__ void __launch_bounds__(256) quant_w_kernel(const float* __restrict__ W) {
    __shared__ uint8_t tile[32][33];
    int n0 = blockIdx.x * 32, k0 = blockIdx.y * 32;
    int tx = threadIdx.x, ty = threadIdx.y;
#pragma unroll
    for (int j = 0; j < 4; j++) {
        int kk = ty + j * 8;
        tile[kk][tx] = (uint8_t)sign_byte(__float_as_uint(W[(size_t)(k0 + kk) * OUT_DIM + n0 + tx]));
    }
    __syncthreads();
    int t = tx + ty * 32;
    int nn = t >> 3;            // 0..31
    int kk = (t & 7) * 4;       // 0..28
    uint32_t p = (uint32_t)tile[kk + 0][nn]
               | ((uint32_t)tile[kk + 1][nn] << 8)
               | ((uint32_t)tile[kk + 2][nn] << 16)
               | ((uint32_t)tile[kk + 3][nn] << 24);
    *reinterpret_cast<uint32_t*>(&g_Wb[(size_t)(n0 + nn) * IN_DIM + k0 + kk]) = p;
}

// ---------------------------------------------------------------------------
// Kernel 3: int8 mma.sync GEMM + fused scale epilogue (round-5 config)
//   D[m,n] = sum_k Xb[m,k]*Wb[n,k] (exact int); out = float(D) * scale[n]
// ---------------------------------------------------------------------------
__global__ void __launch_bounds__(256, 2) gemm_kernel(
    const float* __restrict__ alpha, const float* __restrict__ betta,
    const float* __restrict__ gamma, float* __restrict__ out)
{
    extern __shared__ char smem[];
    uint32_t sb = smem_u32(smem);
    int tid = threadIdx.x, wid = tid >> 5, lane = tid & 31;
    int warp_m = wid >> 2, warp_n = wid & 3;        // 2 x 4 warp grid
    int g = lane >> 2, q = lane & 3;
    int n0 = blockIdx.x * BN, m0 = blockIdx.y * BM;

    if (tid < BN) {   // per-column scale
        int n = n0 + tid;
        float s = fmaxf(__ldg(alpha), 0.f) * fmaxf(__ldg(&betta[n >> 6]), 0.f)
                * fmaxf(__ldg(&gamma[n & 63]), 0.f);
        reinterpret_cast<float*>(smem + SMEM_SCALE)[tid] = s;
    }

    // cp.async fill: 1024 x 16B chunks per stage (512 A + 512 B), 4 per thread
    auto fill = [&](int ks) {
        uint32_t dst = sb + SMEM_AB + (ks & (NBUF - 1)) * STAGE_BYTES;
        size_t ksrc = (size_t)ks * BK;
#pragma unroll
        for (int i = 0; i < 4; i++) {
            int c = tid + i * 256;
            if (c < 512) {
                int row = c >> 2, q16 = c & 3;
                cp_async16(dst + row * ROW_STRIDE + q16 * 16,
                           g_Xb + (size_t)(m0 + row) * IN_DIM + ksrc + q16 * 16);
            } else {
                int c2 = c - 512;
                int row = c2 >> 2, q16 = c2 & 3;
                cp_async16(dst + A_BYTES + row * ROW_STRIDE + q16 * 16,
                           g_Wb + (size_t)(n0 + row) * IN_DIM + ksrc + q16 * 16);
            }
        }
        asm volatile("cp.async.commit_group;" ::: "memory");
    };

    int acc[4][4][4];
#pragma unroll
    for (int mi = 0; mi < 4; mi++)
#pragma unroll
        for (int nj = 0; nj < 4; nj++)
#pragma unroll
            for (int r = 0; r < 4; r++) acc[mi][nj][r] = 0;

    fill(0); fill(1); fill(2);

    for (int ks = 0; ks < KSTEPS; ks++) {
        asm volatile("cp.async.wait_group 2;" ::: "memory");   // stage ks resident
        __syncthreads();

        const char* sA = smem + SMEM_AB + (ks & (NBUF - 1)) * STAGE_BYTES;
        const char* sB = sA + A_BYTES;
#pragma unroll
        for (int kk = 0; kk < 2; kk++) {                       // two k32 steps per BK=64
            int ko = kk * 32;
            uint32_t a[4][4], b[4][2];
#pragma unroll
            for (int mi = 0; mi < 4; mi++) {
                const char* pa = sA + (warp_m * 64 + mi * 16 + g) * ROW_STRIDE + q * 4 + ko;
                a[mi][0] = *reinterpret_cast<const uint32_t*>(pa);
                a[mi][1] = *reinterpret_cast<const uint32_t*>(pa + 8 * ROW_STRIDE);
                a[mi][2] = *reinterpret_cast<const uint32_t*>(pa + 16);
                a[mi][3] = *reinterpret_cast<const uint32_t*>(pa + 8 * ROW_STRIDE + 16);
            }
#pragma unroll
            for (int nj = 0; nj < 4; nj++) {
                const char* pb = sB + (warp_n * 32 + nj * 8 + g) * ROW_STRIDE + q * 4 + ko;
                b[nj][0] = *reinterpret_cast<const uint32_t*>(pb);
                b[nj][1] = *reinterpret_cast<const uint32_t*>(pb + 16);
            }
#pragma unroll
            for (int mi = 0; mi < 4; mi++)
#pragma unroll
                for (int nj = 0; nj < 4; nj++)
                    mma_s8(acc[mi][nj], a[mi], b[nj]);
        }
        // Buffer (ks+3)&3 held stage ks-1, consumed by all warps before the
        // __syncthreads above -> safe to refill without a second barrier.
        if (ks + 3 < KSTEPS) fill(ks + 3);
        else asm volatile("cp.async.commit_group;" ::: "memory");  // uniform accounting
    }

    __syncthreads();
    const float* sc = reinterpret_cast<const float*>(smem + SMEM_SCALE);
#pragma unroll
    for (int mi = 0; mi < 4; mi++) {
        int r0 = m0 + warp_m * 64 + mi * 16 + g;
#pragma unroll
        for (int nj = 0; nj < 4; nj++) {
            int col = warp_n * 32 + nj * 8 + 2 * q;
            float s0 = sc[col], s1 = sc[col + 1];
            float2 v0 = make_float2((float)acc[mi][nj][0] * s0, (float)acc[mi][nj][1] * s1);
            float2 v1 = make_float2((float)acc[mi][nj][2] * s0, (float)acc[mi][nj][3] * s1);
            *reinterpret_cast<float2*>(out + (size_t)r0 * OUT_DIM + n0 + col) = v0;
            *reinterpret_cast<float2*>(out + (size_t)(r0 + 8) * OUT_DIM + n0 + col) = v1;
        }
    }
}

// ---------------------------------------------------------------------------
// Launch
// ---------------------------------------------------------------------------
extern "C" void kernel_launch(void* const* d_in, const int* in_sizes, int n_in,
                              void* d_out, int out_size) {
    const float *X = nullptr, *W = nullptr, *alpha = nullptr, *betta = nullptr, *gamma = nullptr;
    for (int i = 0; i < n_in; i++) {
        switch (in_sizes[i]) {
            case B_DIM * IN_DIM:   X     = (const float*)d_in[i]; break;  // 33554432
            case IN_DIM * OUT_DIM: W     = (const float*)d_in[i]; break;  // 8388608
            case 1:                alpha = (const float*)d_in[i]; break;
            case 32:               betta = (const float*)d_in[i]; break;
            case 64:               gamma = (const float*)d_in[i]; break;
        }
    }
    cudaFuncSetAttribute(gemm_kernel, cudaFuncAttributeMaxDynamicSharedMemorySize, SMEM_TOTAL);

    // quant_x: total uint4 elements = B*IN/4 = 8388608; each block covers
    // 512 low-half + 512 high-half => grid = total / 1024.
    quant_x_kernel<<<(B_DIM * (size_t)IN_DIM) / 4 / 1024, 256>>>(X);
    quant_w_kernel<<<dim3(OUT_DIM / 32, IN_DIM / 32), dim3(32, 8)>>>(W);
    gemm_kernel<<<dim3(OUT_DIM / BN, B_DIM / BM), 256, SMEM_TOTAL>>>(
        alpha, betta, gamma, (float*)d_out);
}